// round 11
// baseline (speedup 1.0000x reference)
#include <cuda_runtime.h>

// ---------------------------------------------------------------------------
// Compile-time rotation table, bit-exact vs the reference (rel_err 0.0 in
// R4/R6/R7/R9/R10). Trig constants are the correctly-rounded libm doubles of
// cos/sin(k*pi_d/4); their 1-ulp asymmetries decide the cancellation-residue
// sign on diagonal positions and hence round(15.5 -/+ eps). Expression shape
// matches Python exactly: fl(fl(ct*x) - fl(st*y)).
// ---------------------------------------------------------------------------
struct Table { int v[1024]; };

constexpr int iround(double v) {
    // == rint here: only exact .5 reachable is 15.5; +0.5 -> 16 = half-even.
    return v >= 0.0 ? (int)(v + 0.5) : -(int)(0.5 - v);
}
constexpr int iclamp31(int v) { return v < 0 ? 0 : (v > 31 ? 31 : v); }

constexpr Table make_table() {
    Table t{};
    for (int c = 0; c < 1024; c++) t.v[c] = -1;
    const double ct[8] = { 1.0,                     0.7071067811865476,
                           6.123233995736766e-17,  -0.7071067811865475,
                          -1.0,                    -0.7071067811865477,
                          -1.8369701987210297e-16,  0.7071067811865474 };
    const double st[8] = { 0.0,                     0.7071067811865475,
                           1.0,                     0.7071067811865476,
                           1.2246467991473532e-16, -0.7071067811865475,
                          -1.0,                    -0.7071067811865477 };
    int idx = 0;
    for (int i = 0; i < 16; i++) {
        for (int j = 31 - i; j < 32; j++) {       // octant: angle in [0, pi/4]
            double y = 15.5 - (double)i;
            double x = (double)j - 15.5;
            for (int k = 0; k < 8; k++) {
                double xn = ct[k] * x - st[k] * y;
                double yn = st[k] * x + ct[k] * y;
                int ir = iclamp31(iround(15.5 - yn));
                int jr = iclamp31(iround(15.5 + xn));
                t.v[ir * 32 + jr] = idx * 8 + k;   // last write wins
            }
            idx++;
        }
    }
    return t;
}

__constant__ constexpr Table TBL = make_table();

// ---------------------------------------------------------------------------
// Fused gather + broadcast-add. 2D grid: blockIdx.x = token (0..1024),
// blockIdx.y = batch-chunk (0..31). Each thread owns one float4 channel slot
// of its token and streams CHUNK=4 batches: out = x + f.
// This round: __stwt (write-through) on out — lines are write-once/never-read,
// so skip L2 dirty staging + eviction, freeing LTS for the read stream.
// Reads stay __ldcs (evict-first; __ldlu measured neutral in R9).
// Granularity saturated at 32800 blocks (80.8% -> 84.5% DRAM series).
// Occupancy supplies MLP (per-thread batching regressed in R4/R5).
// ---------------------------------------------------------------------------
#define P4      262400u            // float4 per batch row (1025*256)
#define CHUNK   4u                 // batches per block
#define NCHUNK  32u                // 128 / CHUNK

__global__ void __launch_bounds__(256) add_posembed_kernel(
    const float4* __restrict__ x,
    const float4* __restrict__ P,     // (136, 8, 128) f32 = 136*256 float4
    const float4* __restrict__ cls,   // 128 f32 = 32 float4
    float4* __restrict__ out)
{
    const int t  = blockIdx.x;          // token 0..1024 (block-uniform)
    const int c4 = threadIdx.x;         // float4 index within 1024 channels

    float4 f;
    if (t == 0) {
        f = cls[c4 & 31];               // CLS tiled across 8 groups
    } else {
        const int packed = TBL.v[t - 1];
        if (packed < 0) {
            f = make_float4(0.f, 0.f, 0.f, 0.f);
        } else {
            const int group = ((c4 >> 5) - (packed & 7)) & 7;
            f = P[(packed >> 3) * 256 + group * 32 + (c4 & 31)];
        }
    }

    unsigned off = blockIdx.y * (CHUNK * P4) + (unsigned)t * 256u + (unsigned)c4;
#pragma unroll
    for (unsigned b = 0; b < CHUNK; b++) {
        float4 v = __ldcs(x + off);
        v.x += f.x; v.y += f.y; v.z += f.z; v.w += f.w;
        __stwt(out + off, v);           // write-through: no L2 dirty staging
        off += P4;
    }
}

extern "C" void kernel_launch(void* const* d_in, const int* in_sizes, int n_in,
                              void* d_out, int out_size) {
    const float4* x   = (const float4*)d_in[0];  // (128, 1025, 1024) f32
    const float4* P   = (const float4*)d_in[1];  // (1, 136, 1024) f32
    const float4* cls = (const float4*)d_in[2];  // (1, 1, 128) f32
    float4* out = (float4*)d_out;

    dim3 grid(1025, NCHUNK);            // 32 chunks x 4 batches = 128
    add_posembed_kernel<<<grid, 256>>>(x, P, cls, out);
}

// round 13
// speedup vs baseline: 1.0170x; 1.0170x over previous
#include <cuda_runtime.h>

// ---------------------------------------------------------------------------
// Compile-time rotation table, bit-exact vs the reference (rel_err 0.0 in
// R4/R6/R7/R9/R10/R11). Trig constants are the correctly-rounded libm doubles
// of cos/sin(k*pi_d/4); their 1-ulp asymmetries decide the cancellation-
// residue sign on diagonal positions and hence round(15.5 -/+ eps).
// Expression shape matches Python exactly: fl(fl(ct*x) - fl(st*y)).
// ---------------------------------------------------------------------------
struct Table { int v[1024]; };

constexpr int iround(double v) {
    // == rint here: only exact .5 reachable is 15.5; +0.5 -> 16 = half-even.
    return v >= 0.0 ? (int)(v + 0.5) : -(int)(0.5 - v);
}
constexpr int iclamp31(int v) { return v < 0 ? 0 : (v > 31 ? 31 : v); }

constexpr Table make_table() {
    Table t{};
    for (int c = 0; c < 1024; c++) t.v[c] = -1;
    const double ct[8] = { 1.0,                     0.7071067811865476,
                           6.123233995736766e-17,  -0.7071067811865475,
                          -1.0,                    -0.7071067811865477,
                          -1.8369701987210297e-16,  0.7071067811865474 };
    const double st[8] = { 0.0,                     0.7071067811865475,
                           1.0,                     0.7071067811865476,
                           1.2246467991473532e-16, -0.7071067811865475,
                          -1.0,                    -0.7071067811865477 };
    int idx = 0;
    for (int i = 0; i < 16; i++) {
        for (int j = 31 - i; j < 32; j++) {       // octant: angle in [0, pi/4]
            double y = 15.5 - (double)i;
            double x = (double)j - 15.5;
            for (int k = 0; k < 8; k++) {
                double xn = ct[k] * x - st[k] * y;
                double yn = st[k] * x + ct[k] * y;
                int ir = iclamp31(iround(15.5 - yn));
                int jr = iclamp31(iround(15.5 + xn));
                t.v[ir * 32 + jr] = idx * 8 + k;   // last write wins
            }
            idx++;
        }
    }
    return t;
}

__constant__ constexpr Table TBL = make_table();

// ---------------------------------------------------------------------------
// Fused gather + broadcast-add. 2D grid: blockIdx.x = token (0..1024),
// blockIdx.y = batch-chunk (0..31). Each thread owns one float4 channel slot
// of its token and streams CHUNK=4 batches: out = x + f.
// CONVERGED CONFIG (measured-best across 11 rounds):
//   - 1-deep ldcs/add/stcs body: occupancy supplies MLP (2/8-deep batching
//     raised regs, cut occupancy, lowered DRAM: R4 79.8%, R5 71.1%)
//   - 32800-block granularity: DRAM series 80.8% -> 84.4% -> 84.5% (saturated)
//   - __ldcs reads (ldlu neutral, R9), __stcs stores (stwt -1.4% DRAM, R11)
//   - constexpr table: zero runtime cost, one graph node, bit-exact
// Pinned at the mixed read/write HBM ceiling: ~6.7 TB/s (84.5% of spec),
// compulsory traffic only (537 MB in + 537 MB out).
// ---------------------------------------------------------------------------
#define P4      262400u            // float4 per batch row (1025*256)
#define CHUNK   4u                 // batches per block
#define NCHUNK  32u                // 128 / CHUNK

__global__ void __launch_bounds__(256) add_posembed_kernel(
    const float4* __restrict__ x,
    const float4* __restrict__ P,     // (136, 8, 128) f32 = 136*256 float4
    const float4* __restrict__ cls,   // 128 f32 = 32 float4
    float4* __restrict__ out)
{
    const int t  = blockIdx.x;          // token 0..1024 (block-uniform)
    const int c4 = threadIdx.x;         // float4 index within 1024 channels

    float4 f;
    if (t == 0) {
        f = cls[c4 & 31];               // CLS tiled across 8 groups
    } else {
        const int packed = TBL.v[t - 1];
        if (packed < 0) {
            f = make_float4(0.f, 0.f, 0.f, 0.f);
        } else {
            const int group = ((c4 >> 5) - (packed & 7)) & 7;
            f = P[(packed >> 3) * 256 + group * 32 + (c4 & 31)];
        }
    }

    unsigned off = blockIdx.y * (CHUNK * P4) + (unsigned)t * 256u + (unsigned)c4;
#pragma unroll
    for (unsigned b = 0; b < CHUNK; b++) {
        float4 v = __ldcs(x + off);
        v.x += f.x; v.y += f.y; v.z += f.z; v.w += f.w;
        __stcs(out + off, v);
        off += P4;
    }
}

extern "C" void kernel_launch(void* const* d_in, const int* in_sizes, int n_in,
                              void* d_out, int out_size) {
    const float4* x   = (const float4*)d_in[0];  // (128, 1025, 1024) f32
    const float4* P   = (const float4*)d_in[1];  // (1, 136, 1024) f32
    const float4* cls = (const float4*)d_in[2];  // (1, 1, 128) f32
    float4* out = (float4*)d_out;

    dim3 grid(1025, NCHUNK);            // 32 chunks x 4 batches = 128
    add_posembed_kernel<<<grid, 256>>>(x, P, cls, out);
}

// round 14
// speedup vs baseline: 1.0187x; 1.0016x over previous
#include <cuda_runtime.h>

// ---------------------------------------------------------------------------
// Compile-time rotation table, bit-exact vs the reference (rel_err 0.0 in
// R4/R6/R7/R9/R10/R11/R13). Trig constants are the correctly-rounded libm
// doubles of cos/sin(k*pi_d/4); their 1-ulp asymmetries decide the
// cancellation-residue sign on diagonal positions and hence
// round(15.5 -/+ eps). Expression shape matches Python exactly.
// ---------------------------------------------------------------------------
struct Table { int v[1024]; };

constexpr int iround(double v) {
    // == rint here: only exact .5 reachable is 15.5; +0.5 -> 16 = half-even.
    return v >= 0.0 ? (int)(v + 0.5) : -(int)(0.5 - v);
}
constexpr int iclamp31(int v) { return v < 0 ? 0 : (v > 31 ? 31 : v); }

constexpr Table make_table() {
    Table t{};
    for (int c = 0; c < 1024; c++) t.v[c] = -1;
    const double ct[8] = { 1.0,                     0.7071067811865476,
                           6.123233995736766e-17,  -0.7071067811865475,
                          -1.0,                    -0.7071067811865477,
                          -1.8369701987210297e-16,  0.7071067811865474 };
    const double st[8] = { 0.0,                     0.7071067811865475,
                           1.0,                     0.7071067811865476,
                           1.2246467991473532e-16, -0.7071067811865475,
                          -1.0,                    -0.7071067811865477 };
    int idx = 0;
    for (int i = 0; i < 16; i++) {
        for (int j = 31 - i; j < 32; j++) {       // octant: angle in [0, pi/4]
            double y = 15.5 - (double)i;
            double x = (double)j - 15.5;
            for (int k = 0; k < 8; k++) {
                double xn = ct[k] * x - st[k] * y;
                double yn = st[k] * x + ct[k] * y;
                int ir = iclamp31(iround(15.5 - yn));
                int jr = iclamp31(iround(15.5 + xn));
                t.v[ir * 32 + jr] = idx * 8 + k;   // last write wins
            }
            idx++;
        }
    }
    return t;
}

__constant__ constexpr Table TBL = make_table();

// ---------------------------------------------------------------------------
// Fused gather + broadcast-add. 2D grid: blockIdx.x = token (0..1024),
// blockIdx.y = batch-chunk (0..63). Each thread owns one float4 channel slot
// of its token and streams CHUNK=2 batches: out = x + f.
// Final granularity point: 1025 blk -> 80.8% DRAM, 16400 -> 84.4%,
// 32800 -> 84.5% (best total 155.7); this probes 65600 (tail quantum halved
// again; P re-gathers stay pure L2 hits, P = 139 KB resident).
// 1-deep ldcs/add/stcs body: occupancy supplies MLP (deeper per-thread
// batching regressed in R4/R5). __ldcs/__stcs proven best (R9/R11).
// ---------------------------------------------------------------------------
#define P4      262400u            // float4 per batch row (1025*256)
#define CHUNK   2u                 // batches per block
#define NCHUNK  64u                // 128 / CHUNK

__global__ void __launch_bounds__(256) add_posembed_kernel(
    const float4* __restrict__ x,
    const float4* __restrict__ P,     // (136, 8, 128) f32 = 136*256 float4
    const float4* __restrict__ cls,   // 128 f32 = 32 float4
    float4* __restrict__ out)
{
    const int t  = blockIdx.x;          // token 0..1024 (block-uniform)
    const int c4 = threadIdx.x;         // float4 index within 1024 channels

    float4 f;
    if (t == 0) {
        f = cls[c4 & 31];               // CLS tiled across 8 groups
    } else {
        const int packed = TBL.v[t - 1];
        if (packed < 0) {
            f = make_float4(0.f, 0.f, 0.f, 0.f);
        } else {
            const int group = ((c4 >> 5) - (packed & 7)) & 7;
            f = P[(packed >> 3) * 256 + group * 32 + (c4 & 31)];
        }
    }

    unsigned off = blockIdx.y * (CHUNK * P4) + (unsigned)t * 256u + (unsigned)c4;
#pragma unroll
    for (unsigned b = 0; b < CHUNK; b++) {
        float4 v = __ldcs(x + off);
        v.x += f.x; v.y += f.y; v.z += f.z; v.w += f.w;
        __stcs(out + off, v);
        off += P4;
    }
}

extern "C" void kernel_launch(void* const* d_in, const int* in_sizes, int n_in,
                              void* d_out, int out_size) {
    const float4* x   = (const float4*)d_in[0];  // (128, 1025, 1024) f32
    const float4* P   = (const float4*)d_in[1];  // (1, 136, 1024) f32
    const float4* cls = (const float4*)d_in[2];  // (1, 1, 128) f32
    float4* out = (float4*)d_out;

    dim3 grid(1025, NCHUNK);            // 64 chunks x 2 batches = 128
    add_posembed_kernel<<<grid, 256>>>(x, P, cls, out);
}

// round 17
// speedup vs baseline: 1.0262x; 1.0074x over previous
#include <cuda_runtime.h>

// ---------------------------------------------------------------------------
// FINAL KERNEL — converged after 14 rounds of measurement.
//
// Compile-time rotation table, bit-exact vs the reference (rel_err 0.0 on all
// passing rounds). Trig constants are the correctly-rounded libm doubles of
// cos/sin(k*pi_d/4); their 1-ulp asymmetries decide the cancellation-residue
// sign on diagonal positions and hence round(15.5 -/+ eps). Expression shape
// matches Python exactly: fl(fl(ct*x) - fl(st*y)).
// ---------------------------------------------------------------------------
struct Table { int v[1024]; };

constexpr int iround(double v) {
    // == rint here: only exact .5 reachable is 15.5; +0.5 -> 16 = half-even.
    return v >= 0.0 ? (int)(v + 0.5) : -(int)(0.5 - v);
}
constexpr int iclamp31(int v) { return v < 0 ? 0 : (v > 31 ? 31 : v); }

constexpr Table make_table() {
    Table t{};
    for (int c = 0; c < 1024; c++) t.v[c] = -1;
    const double ct[8] = { 1.0,                     0.7071067811865476,
                           6.123233995736766e-17,  -0.7071067811865475,
                          -1.0,                    -0.7071067811865477,
                          -1.8369701987210297e-16,  0.7071067811865474 };
    const double st[8] = { 0.0,                     0.7071067811865475,
                           1.0,                     0.7071067811865476,
                           1.2246467991473532e-16, -0.7071067811865475,
                          -1.0,                    -0.7071067811865477 };
    int idx = 0;
    for (int i = 0; i < 16; i++) {
        for (int j = 31 - i; j < 32; j++) {       // octant: angle in [0, pi/4]
            double y = 15.5 - (double)i;
            double x = (double)j - 15.5;
            for (int k = 0; k < 8; k++) {
                double xn = ct[k] * x - st[k] * y;
                double yn = st[k] * x + ct[k] * y;
                int ir = iclamp31(iround(15.5 - yn));
                int jr = iclamp31(iround(15.5 + xn));
                t.v[ir * 32 + jr] = idx * 8 + k;   // last write wins
            }
            idx++;
        }
    }
    return t;
}

__constant__ constexpr Table TBL = make_table();

// ---------------------------------------------------------------------------
// Fused gather + broadcast-add. 2D grid: blockIdx.x = token (0..1024),
// blockIdx.y = batch-chunk (0..31). Each thread owns one float4 channel slot
// of its token and streams CHUNK=4 batches: out = x + f.
//
// CONVERGED CONFIG — every axis measured:
//   - MLP depth 1/2/8: 1-deep wins; occupancy supplies MLP (deeper batching
//     raised regs 30->40/48, cut occ to 65/53%, cut DRAM to 71/80%)
//   - granularity 1025/1184/16400/32800/65600 blocks: 32800 optimal
//     (DRAM 80.8% -> 84.4% -> 84.5%, flat beyond)
//   - __ldcs reads (ldlu neutral), __stcs stores (stwt -1.4% DRAM)
//   - constexpr table: zero runtime cost, single graph node, bit-exact
// Pinned at the mixed read/write HBM ceiling: ~6.7 TB/s (84.5% of spec),
// compulsory traffic only (537 MB in + 537 MB out; P gathers L2-resident).
// ---------------------------------------------------------------------------
#define P4      262400u            // float4 per batch row (1025*256)
#define CHUNK   4u                 // batches per block
#define NCHUNK  32u                // 128 / CHUNK

__global__ void __launch_bounds__(256) add_posembed_kernel(
    const float4* __restrict__ x,
    const float4* __restrict__ P,     // (136, 8, 128) f32 = 136*256 float4
    const float4* __restrict__ cls,   // 128 f32 = 32 float4
    float4* __restrict__ out)
{
    const int t  = blockIdx.x;          // token 0..1024 (block-uniform)
    const int c4 = threadIdx.x;         // float4 index within 1024 channels

    float4 f;
    if (t == 0) {
        f = cls[c4 & 31];               // CLS tiled across 8 groups
    } else {
        const int packed = TBL.v[t - 1];
        if (packed < 0) {
            f = make_float4(0.f, 0.f, 0.f, 0.f);
        } else {
            const int group = ((c4 >> 5) - (packed & 7)) & 7;
            f = P[(packed >> 3) * 256 + group * 32 + (c4 & 31)];
        }
    }

    unsigned off = blockIdx.y * (CHUNK * P4) + (unsigned)t * 256u + (unsigned)c4;
#pragma unroll
    for (unsigned b = 0; b < CHUNK; b++) {
        float4 v = __ldcs(x + off);
        v.x += f.x; v.y += f.y; v.z += f.z; v.w += f.w;
        __stcs(out + off, v);
        off += P4;
    }
}

extern "C" void kernel_launch(void* const* d_in, const int* in_sizes, int n_in,
                              void* d_out, int out_size) {
    const float4* x   = (const float4*)d_in[0];  // (128, 1025, 1024) f32
    const float4* P   = (const float4*)d_in[1];  // (1, 136, 1024) f32
    const float4* cls = (const float4*)d_in[2];  // (1, 1, 128) f32
    float4* out = (float4*)d_out;

    dim3 grid(1025, NCHUNK);            // 32 chunks x 4 batches = 128
    add_posembed_kernel<<<grid, 256>>>(x, P, cls, out);
}